// round 16
// baseline (speedup 1.0000x reference)
#include <cuda_runtime.h>
#include <cuda_bf16.h>
#include <stdint.h>

#define NN    50000
#define FIN   512
#define FH    128
#define FO    40
#define FC    256
#define MPAD  50048           // 391 * 128
#define MT    391
#define EMAX  800000

// ---------------- scratch (device globals; no allocation allowed) ----------
__device__ int   g_cnt[NN];
__device__ int   g_rowptr[NN + 1];
__device__ int   g_woff[NN];
__device__ int   g_eidx[EMAX];
__device__ float g_dis[NN];
__device__ float g_h2[NN * FH];
__device__ float g_hs3[NN * FO];
__device__ float g_h3[NN * FO];
__device__ float g_hp[NN * FO];
__device__ float g_c1[NN * FC];
__device__ float g_c2[NN * FC];
__device__ float g_c3[NN * FO];
__device__ __nv_bfloat16 g_xb[(size_t)MPAD * FIN];   // x bf16; later: L2 GCN A
__device__ __nv_bfloat16 g_ob[(size_t)MPAD * FIN];   // omega bf16; later: L2 comp A
__device__ __nv_bfloat16 g_w1[FH * FIN];
__device__ __nv_bfloat16 g_w2[FH * FH];
__device__ __nv_bfloat16 g_wc1[FC * FIN];
__device__ __nv_bfloat16 g_wc2[FC * FC];
__device__ __nv_bfloat16 g_hsb1[NN * FH];            // bf16 hs1 (sole copy)
__device__ __nv_bfloat16 g_hsb2[NN * FH];            // bf16 hs2 (sole copy)

// ---------------- threefry2x32 (JAX-compatible, partitionable) -------------
__host__ __device__ __forceinline__ void threefry2x32(uint32_t k0, uint32_t k1,
                                                      uint32_t& x0, uint32_t& x1) {
    uint32_t ks0 = k0, ks1 = k1, ks2 = k0 ^ k1 ^ 0x1BD11BDAu;
    x0 += ks0; x1 += ks1;
#define TF_RND(r) { x0 += x1; x1 = (x1 << (r)) | (x1 >> (32 - (r))); x1 ^= x0; }
    TF_RND(13) TF_RND(15) TF_RND(26) TF_RND(6)   x0 += ks1; x1 += ks2 + 1u;
    TF_RND(17) TF_RND(29) TF_RND(16) TF_RND(24)  x0 += ks2; x1 += ks0 + 2u;
    TF_RND(13) TF_RND(15) TF_RND(26) TF_RND(6)   x0 += ks0; x1 += ks1 + 3u;
    TF_RND(17) TF_RND(29) TF_RND(16) TF_RND(24)  x0 += ks1; x1 += ks2 + 4u;
    TF_RND(13) TF_RND(15) TF_RND(26) TF_RND(6)   x0 += ks2; x1 += ks0 + 5u;
#undef TF_RND
}

__device__ __forceinline__ bool tf_keep(uint32_t k0, uint32_t k1, uint32_t idx) {
    uint32_t x0 = 0u, x1 = idx;
    threefry2x32(k0, k1, x0, x1);
    return (((x0 ^ x1) >> 31) == 0u);
}

__device__ __forceinline__ void red_add_v4(float* p, float4 v) {
    asm volatile("red.global.add.v4.f32 [%0], {%1, %2, %3, %4};"
                 :: "l"(p), "f"(v.x), "f"(v.y), "f"(v.z), "f"(v.w) : "memory");
}

__device__ __forceinline__ uint32_t smem_u32(const void* p) {
    uint32_t a;
    asm("{ .reg .u64 t; cvta.to.shared.u64 t, %1; cvt.u32.u64 %0, t; }" : "=r"(a) : "l"(p));
    return a;
}

__device__ __forceinline__ void ldsm_x4(uint32_t* r, uint32_t addr) {
    asm volatile("ldmatrix.sync.aligned.m8n8.x4.shared.b16 {%0,%1,%2,%3}, [%4];"
                 : "=r"(r[0]), "=r"(r[1]), "=r"(r[2]), "=r"(r[3]) : "r"(addr));
}

__device__ __forceinline__ void mma16816(float* c, const uint32_t* a, const uint32_t* b) {
    asm volatile("mma.sync.aligned.m16n8k16.row.col.f32.bf16.bf16.f32 "
                 "{%0,%1,%2,%3}, {%4,%5,%6,%7}, {%8,%9}, {%0,%1,%2,%3};"
                 : "+f"(c[0]), "+f"(c[1]), "+f"(c[2]), "+f"(c[3])
                 : "r"(a[0]), "r"(a[1]), "r"(a[2]), "r"(a[3]), "r"(b[0]), "r"(b[1]));
}

__device__ __forceinline__ void cp_async16(uint32_t saddr, const void* gaddr) {
    asm volatile("cp.async.cg.shared.global [%0], [%1], 16;" :: "r"(saddr), "l"(gaddr));
}
#define CP_COMMIT() asm volatile("cp.async.commit_group;" ::: "memory")
#define CP_WAIT(n)  asm volatile("cp.async.wait_group %0;" :: "n"(n) : "memory")

// ---------------- CSR build --------------------------------------------------
__global__ void __launch_bounds__(1024) k_scan() {
    __shared__ int part[1024];
    int tid = threadIdx.x;
    const int CH = (NN + 1023) / 1024;
    int lo = tid * CH, hi = lo + CH > NN ? NN : lo + CH;
    int s = 0;
    for (int i = lo; i < hi; i++) s += g_cnt[i];
    part[tid] = s;
    __syncthreads();
    for (int off = 1; off < 1024; off <<= 1) {
        int t = (tid >= off) ? part[tid - off] : 0;
        __syncthreads();
        part[tid] += t;
        __syncthreads();
    }
    int run = part[tid] - s;
    for (int i = lo; i < hi; i++) {
        g_rowptr[i] = run;
        g_woff[i]   = run;
        g_dis[i]    = rsqrtf(1.0f + (float)g_cnt[i]);
        run += g_cnt[i];
    }
    if (tid == 1023) g_rowptr[NN] = run;
}

__global__ void k_scatter(const int* __restrict__ src, const int* __restrict__ dst, int E) {
    int i = blockIdx.x * blockDim.x + threadIdx.x;
    if (i >= E) return;
    int pos = atomicAdd(&g_woff[dst[i]], 1);
    g_eidx[pos] = src[i];
}

// ---------------- merged convert + W-split + hist pass ----------------------
__device__ __forceinline__ void convA_item4(const float* A, __nv_bfloat16* out,
                                            int K, long long i) {
    int K4 = K >> 2;
    int r = (int)(i / K4), kk = (int)(i - (long long)r * K4) * 4;
    __nv_bfloat162 h01, h23;
    if (r < NN) {
        float4 a = *reinterpret_cast<const float4*>(A + (size_t)r * K + kk);
        h01 = __halves2bfloat162(__float2bfloat16(a.x), __float2bfloat16(a.y));
        h23 = __halves2bfloat162(__float2bfloat16(a.z), __float2bfloat16(a.w));
    } else {
        __nv_bfloat16 z = __float2bfloat16(0.f);
        h01 = __halves2bfloat162(z, z); h23 = h01;
    }
    uint2 hv;
    hv.x = *reinterpret_cast<uint32_t*>(&h01);
    hv.y = *reinterpret_cast<uint32_t*>(&h23);
    *reinterpret_cast<uint2*>(out + (size_t)r * K + kk) = hv;
}

__device__ __forceinline__ void splitW_item(const float* W, __nv_bfloat16* out,
                                            int K, int N, int i) {
    int k = i / N, n = i - k * N;
    out[(size_t)n * K + k] = __float2bfloat16(W[(size_t)k * N + n]);
}

__global__ void k_split_all(const float* __restrict__ x, const float* __restrict__ omega,
                            const float* __restrict__ Wg1, const float* __restrict__ Wg2,
                            const float* __restrict__ Wc1, const float* __restrict__ Wc2,
                            const int* __restrict__ dst, int E) {
    const long long R0 = (long long)MPAD * (FIN / 4);
    const long long R1 = R0;
    const long long R2 = FIN * FH, R3 = FH * FH;
    const long long R4 = FIN * FC, R5 = FC * FC;
    long long i = (long long)blockIdx.x * blockDim.x + threadIdx.x;
    if (i < R0) { convA_item4(x, g_xb, FIN, i); return; }
    i -= R0;
    if (i < R1) { convA_item4(omega, g_ob, FIN, i); return; }
    i -= R1;
    if (i < R2) { splitW_item(Wg1, g_w1, FIN, FH, (int)i); return; }
    i -= R2;
    if (i < R3) { splitW_item(Wg2, g_w2, FH, FH, (int)i); return; }
    i -= R3;
    if (i < R4) { splitW_item(Wc1, g_wc1, FIN, FC, (int)i); return; }
    i -= R4;
    if (i < R5) { splitW_item(Wc2, g_wc2, FC, FC, (int)i); return; }
    i -= R5;
    if (i < E) { atomicAdd(&g_cnt[dst[(int)i]], 1); return; }
}

// ---------------- bf16 GEMM (cp.async double-buffered) ----------------------
struct GemmP {
    const __nv_bfloat16* A; const __nv_bfloat16* B; const float* bias; float* C;
    __nv_bfloat16* Cb;
    int M, K, N, scale, relu;
};

__device__ __forceinline__ void gemm_body(const GemmP& p, int bm, int bn) {
    __shared__ __align__(16) __nv_bfloat16 As[2][128][72];
    __shared__ __align__(16) __nv_bfloat16 Bs[2][128][72];

    int tid = threadIdx.x, wid = tid >> 5, lane = tid & 31;
    int wm = (wid & 3) << 5;
    int wn = (wid >> 2) << 6;

    float acc[2][8][4];
#pragma unroll
    for (int i = 0; i < 2; i++)
#pragma unroll
        for (int j = 0; j < 8; j++)
#pragma unroll
            for (int q = 0; q < 4; q++) acc[i][j][q] = 0.0f;

    int mat = lane >> 3, r8 = lane & 7;
    int nT = p.K >> 6;

    auto load_tile = [&](int t, int buf) {
        int k0 = t << 6;
#pragma unroll
        for (int i = 0; i < 4; i++) {
            int idx = tid + i * 256;
            int r = idx >> 3, c = idx & 7;
            cp_async16(smem_u32(&As[buf][r][c * 8]),
                       p.A + (size_t)(bm + r) * p.K + k0 + c * 8);
            cp_async16(smem_u32(&Bs[buf][r][c * 8]),
                       p.B + (size_t)(bn + r) * p.K + k0 + c * 8);
        }
        CP_COMMIT();
    };

    load_tile(0, 0);

    for (int t = 0; t < nT; t++) {
        int cur = t & 1;
        if (t + 1 < nT) {
            load_tile(t + 1, cur ^ 1);
            CP_WAIT(1);
        } else {
            CP_WAIT(0);
        }
        __syncthreads();

#pragma unroll
        for (int kk = 0; kk < 64; kk += 16) {
            uint32_t a[2][4];
#pragma unroll
            for (int mf = 0; mf < 2; mf++) {
                uint32_t addr = smem_u32(
                    &As[cur][wm + mf * 16 + ((mat & 1) << 3) + r8][kk + ((mat >> 1) << 3)]);
                ldsm_x4(a[mf], addr);
            }
            uint32_t b[8][2];
#pragma unroll
            for (int nf2 = 0; nf2 < 4; nf2++) {
                uint32_t addr = smem_u32(
                    &Bs[cur][wn + nf2 * 16 + ((mat >> 1) << 3) + r8][kk + ((mat & 1) << 3)]);
                uint32_t tr[4];
                ldsm_x4(tr, addr);
                b[nf2 * 2][0] = tr[0]; b[nf2 * 2][1] = tr[1];
                b[nf2 * 2 + 1][0] = tr[2]; b[nf2 * 2 + 1][1] = tr[3];
            }
#pragma unroll
            for (int mf = 0; mf < 2; mf++)
#pragma unroll
                for (int nf = 0; nf < 8; nf++)
                    mma16816(acc[mf][nf], a[mf], b[nf]);
        }
        __syncthreads();
    }

    int g = lane >> 2, tg = lane & 3;
#pragma unroll
    for (int mf = 0; mf < 2; mf++) {
#pragma unroll
        for (int half = 0; half < 2; half++) {
            int r = bm + wm + mf * 16 + g + half * 8;
            if (r >= p.M) continue;
            float sc = p.scale ? g_dis[r] : 1.0f;
#pragma unroll
            for (int nf = 0; nf < 8; nf++) {
                int c = bn + wn + nf * 8 + tg * 2;
                float v0 = acc[mf][nf][half * 2 + 0];
                float v1 = acc[mf][nf][half * 2 + 1];
                if (p.bias) { v0 += p.bias[c]; v1 += p.bias[c + 1]; }
                if (p.relu) { v0 = fmaxf(v0, 0.0f); v1 = fmaxf(v1, 0.0f); }
                if (p.scale) { v0 *= sc; v1 *= sc; }
                if (p.C)
                    *reinterpret_cast<float2*>(&p.C[(size_t)r * p.N + c]) = make_float2(v0, v1);
                if (p.Cb)
                    *reinterpret_cast<__nv_bfloat162*>(&p.Cb[(size_t)r * p.N + c]) =
                        __halves2bfloat162(__float2bfloat16(v0), __float2bfloat16(v1));
            }
        }
    }
}

__global__ void __launch_bounds__(256, 2)
k_gemm_fat(GemmP pa, GemmP pb, int yA, int yTot) {
    int b = blockIdx.x;
    int y = b % yTot, m = b / yTot;
    if (y < yA) gemm_body(pa, m * 128, y * 128);
    else        gemm_body(pb, m * 128, (y - yA) * 128);
}

// ---------------- SGEMM 64x64x16 fp32 (N=40), parametrized bm ---------------
struct SgP {
    const float* A; const float* W; const float* bias; float* C;
    int K, scale, drop;
    uint32_t dk0, dk1;
};

__device__ __forceinline__ void sgemm_body(const SgP& p, int bmBlk) {
    const int BM = 64, BN = 64, BK = 16, N = FO;
    __shared__ float As[BK][BM + 4];
    __shared__ float Ws[BK][BN];

    int tid = threadIdx.x;
    int bm = bmBlk * BM;
    int tx = tid & 15, ty = tid >> 4;
    int arow = tid >> 2, acol4 = tid & 3;
    int wrow = tid >> 4, wcol4 = tid & 15;

    float acc[4][4];
#pragma unroll
    for (int i = 0; i < 4; i++)
#pragma unroll
        for (int j = 0; j < 4; j++) acc[i][j] = 0.0f;

    for (int k0 = 0; k0 < p.K; k0 += BK) {
        float4 av = make_float4(0.f, 0.f, 0.f, 0.f);
        int gr = bm + arow;
        if (gr < NN) {
            av = *reinterpret_cast<const float4*>(&p.A[(size_t)gr * p.K + k0 + acol4 * 4]);
            if (p.drop) {
                uint32_t e0 = (uint32_t)gr * p.K + k0 + acol4 * 4;
                av.x = tf_keep(p.dk0, p.dk1, e0)      ? 2.0f * av.x : 0.0f;
                av.y = tf_keep(p.dk0, p.dk1, e0 + 1u) ? 2.0f * av.y : 0.0f;
                av.z = tf_keep(p.dk0, p.dk1, e0 + 2u) ? 2.0f * av.z : 0.0f;
                av.w = tf_keep(p.dk0, p.dk1, e0 + 3u) ? 2.0f * av.w : 0.0f;
            }
        }
        As[acol4 * 4 + 0][arow] = av.x;
        As[acol4 * 4 + 1][arow] = av.y;
        As[acol4 * 4 + 2][arow] = av.z;
        As[acol4 * 4 + 3][arow] = av.w;

        float4 wv = make_float4(0.f, 0.f, 0.f, 0.f);
        int gc = wcol4 * 4;
        if (gc < N)
            wv = *reinterpret_cast<const float4*>(&p.W[(size_t)(k0 + wrow) * N + gc]);
        Ws[wrow][wcol4 * 4 + 0] = wv.x;
        Ws[wrow][wcol4 * 4 + 1] = wv.y;
        Ws[wrow][wcol4 * 4 + 2] = wv.z;
        Ws[wrow][wcol4 * 4 + 3] = wv.w;

        __syncthreads();
#pragma unroll
        for (int k = 0; k < BK; k++) {
            float a[4], w[4];
#pragma unroll
            for (int i = 0; i < 4; i++) a[i] = As[k][ty * 4 + i];
#pragma unroll
            for (int j = 0; j < 4; j++) w[j] = Ws[k][tx * 4 + j];
#pragma unroll
            for (int i = 0; i < 4; i++)
#pragma unroll
                for (int j = 0; j < 4; j++) acc[i][j] = fmaf(a[i], w[j], acc[i][j]);
        }
        __syncthreads();
    }

#pragma unroll
    for (int i = 0; i < 4; i++) {
        int r = bm + ty * 4 + i;
        if (r >= NN) continue;
        float sc = p.scale ? g_dis[r] : 1.0f;
#pragma unroll
        for (int j = 0; j < 4; j++) {
            int c = tx * 4 + j;
            if (c >= N) continue;
            float v = acc[i][j];
            if (p.bias) v += p.bias[c];
            if (p.scale) v *= sc;
            p.C[(size_t)r * N + c] = v;
        }
    }
}

__global__ void k_sgemm(SgP pa) { sgemm_body(pa, blockIdx.x); }

// ---------------- CSR warp-gather (4x unrolled) for F=128 -------------------
__device__ __forceinline__ float4 bf16x4_to_f4(uint2 u) {
    __nv_bfloat162 p0 = *reinterpret_cast<__nv_bfloat162*>(&u.x);
    __nv_bfloat162 p1 = *reinterpret_cast<__nv_bfloat162*>(&u.y);
    return make_float4(__bfloat162float(p0.x), __bfloat162float(p0.y),
                       __bfloat162float(p1.x), __bfloat162float(p1.y));
}

__device__ __forceinline__ void f4_add(float4& a, float4 b) {
    a.x += b.x; a.y += b.y; a.z += b.z; a.w += b.w;
}

__device__ __forceinline__ float4 csr_gather128(const __nv_bfloat16* hsb, int node, int lane) {
    int beg = g_rowptr[node], end = g_rowptr[node + 1];
    float4 a0 = make_float4(0.f, 0.f, 0.f, 0.f), a1 = a0, a2 = a0, a3 = a0;
    int e = beg;
    for (; e + 4 <= end; e += 4) {
        int s0 = g_eidx[e], s1 = g_eidx[e + 1], s2 = g_eidx[e + 2], s3 = g_eidx[e + 3];
        uint2 u0 = __ldg(reinterpret_cast<const uint2*>(hsb + (size_t)s0 * 128 + lane * 4));
        uint2 u1 = __ldg(reinterpret_cast<const uint2*>(hsb + (size_t)s1 * 128 + lane * 4));
        uint2 u2 = __ldg(reinterpret_cast<const uint2*>(hsb + (size_t)s2 * 128 + lane * 4));
        uint2 u3 = __ldg(reinterpret_cast<const uint2*>(hsb + (size_t)s3 * 128 + lane * 4));
        f4_add(a0, bf16x4_to_f4(u0));
        f4_add(a1, bf16x4_to_f4(u1));
        f4_add(a2, bf16x4_to_f4(u2));
        f4_add(a3, bf16x4_to_f4(u3));
    }
    for (; e < end; e++) {
        int s = g_eidx[e];
        f4_add(a0, bf16x4_to_f4(
            __ldg(reinterpret_cast<const uint2*>(hsb + (size_t)s * 128 + lane * 4))));
    }
    f4_add(a0, a1); f4_add(a2, a3); f4_add(a0, a2);
    return a0;
}

// fat: L1 CSR agg+finish -> bf16 A (L2)  ||  comp dropout c1 -> bf16 A (L2)
__global__ void k_csr1(const __nv_bfloat16* __restrict__ hsb,
                       const float* __restrict__ b, __nv_bfloat16* __restrict__ out,
                       uint32_t k0, uint32_t k1, int nodeBlocks,
                       const float* __restrict__ cin, __nv_bfloat16* __restrict__ aout,
                       uint32_t ck0, uint32_t ck1) {
    if ((int)blockIdx.x < nodeBlocks) {
        int node = blockIdx.x * 8 + (threadIdx.x >> 5);
        if (node >= NN) return;
        int lane = threadIdx.x & 31;
        float4 acc = csr_gather128(hsb, node, lane);
        float di = g_dis[node];
        int base = node * 128 + lane * 4;
        float4 h = bf16x4_to_f4(*reinterpret_cast<const uint2*>(hsb + base));
        float4 bb = *reinterpret_cast<const float4*>(b + lane * 4);
        float v[4] = { di * (acc.x + h.x) + bb.x, di * (acc.y + h.y) + bb.y,
                       di * (acc.z + h.z) + bb.z, di * (acc.w + h.w) + bb.w };
        __nv_bfloat16 hi[4];
#pragma unroll
        for (int j = 0; j < 4; j++) {
            float t = fmaxf(v[j], 0.0f);
            t = tf_keep(k0, k1, (uint32_t)(base + j)) ? 2.0f * t : 0.0f;
            hi[j] = __float2bfloat16(t);
        }
        *reinterpret_cast<__nv_bfloat162*>(out + base)     = __halves2bfloat162(hi[0], hi[1]);
        *reinterpret_cast<__nv_bfloat162*>(out + base + 2) = __halves2bfloat162(hi[2], hi[3]);
    } else {
        int e = (blockIdx.x - nodeBlocks) * blockDim.x + threadIdx.x;
        if (e >= MPAD * FC) return;
        int r = e >> 8;
        __nv_bfloat16 h = __float2bfloat16(0.f);
        if (r < NN) {
            float v = tf_keep(ck0, ck1, (uint32_t)e) ? 2.0f * cin[e] : 0.0f;
            h = __float2bfloat16(v);
        }
        aout[e] = h;
    }
}

// fat: L2 CSR agg+finish -> fp32 h2  ||  comp L3 sgemm (dropout(c2) @ Wc3)
__global__ void k_csr2_sg(const __nv_bfloat16* __restrict__ hsb,
                          const float* __restrict__ b, float* __restrict__ out,
                          uint32_t k0, uint32_t k1, int nodeBlocks, SgP sg) {
    if ((int)blockIdx.x < nodeBlocks) {
        int node = blockIdx.x * 8 + (threadIdx.x >> 5);
        if (node >= NN) return;
        int lane = threadIdx.x & 31;
        float4 acc = csr_gather128(hsb, node, lane);
        float di = g_dis[node];
        int base = node * 128 + lane * 4;
        float4 h = bf16x4_to_f4(*reinterpret_cast<const uint2*>(hsb + base));
        float4 bb = *reinterpret_cast<const float4*>(b + lane * 4);
        float4 o;
        o.x = di * (acc.x + h.x) + bb.x;
        o.y = di * (acc.y + h.y) + bb.y;
        o.z = di * (acc.z + h.z) + bb.z;
        o.w = di * (acc.w + h.w) + bb.w;
        o.x = tf_keep(k0, k1, (uint32_t)(base + 0)) ? 2.0f * fmaxf(o.x, 0.f) : 0.0f;
        o.y = tf_keep(k0, k1, (uint32_t)(base + 1)) ? 2.0f * fmaxf(o.y, 0.f) : 0.0f;
        o.z = tf_keep(k0, k1, (uint32_t)(base + 2)) ? 2.0f * fmaxf(o.z, 0.f) : 0.0f;
        o.w = tf_keep(k0, k1, (uint32_t)(base + 3)) ? 2.0f * fmaxf(o.w, 0.f) : 0.0f;
        *reinterpret_cast<float4*>(out + base) = o;
    } else {
        sgemm_body(sg, blockIdx.x - nodeBlocks);
    }
}

// L3: thread per (node, q<10): CSR gather float4 (4x unroll) + finish -> h3
__global__ void k_csr3(const float* __restrict__ hs, const float* __restrict__ b) {
    int t = blockIdx.x * blockDim.x + threadIdx.x;
    if (t >= NN * 10) return;
    int node = t / 10, q = t - node * 10;
    int beg = g_rowptr[node], end = g_rowptr[node + 1];
    float4 a0 = make_float4(0.f, 0.f, 0.f, 0.f), a1 = a0, a2 = a0, a3 = a0;
    int e = beg;
    for (; e + 4 <= end; e += 4) {
        int s0 = g_eidx[e], s1 = g_eidx[e + 1], s2 = g_eidx[e + 2], s3 = g_eidx[e + 3];
        float4 v0 = __ldg(reinterpret_cast<const float4*>(hs) + (size_t)s0 * 10 + q);
        float4 v1 = __ldg(reinterpret_cast<const float4*>(hs) + (size_t)s1 * 10 + q);
        float4 v2 = __ldg(reinterpret_cast<const float4*>(hs) + (size_t)s2 * 10 + q);
        float4 v3 = __ldg(reinterpret_cast<const float4*>(hs) + (size_t)s3 * 10 + q);
        f4_add(a0, v0); f4_add(a1, v1); f4_add(a2, v2); f4_add(a3, v3);
    }
    for (; e < end; e++) {
        int s = g_eidx[e];
        f4_add(a0, __ldg(reinterpret_cast<const float4*>(hs) + (size_t)s * 10 + q));
    }
    f4_add(a0, a1); f4_add(a2, a3); f4_add(a0, a2);
    float di = g_dis[node];
    float4 h = __ldg(reinterpret_cast<const float4*>(hs) + (size_t)node * 10 + q);
    float4 bb = *reinterpret_cast<const float4*>(b + q * 4);
    float4 o;
    o.x = di * (a0.x + h.x) + bb.x;
    o.y = di * (a0.y + h.y) + bb.y;
    o.z = di * (a0.z + h.z) + bb.z;
    o.w = di * (a0.w + h.w) + bb.w;
    *reinterpret_cast<float4*>(g_h3 + (size_t)node * 40 + q * 4) = o;
}

// ---------------- SpMM -------------------------------------------------------
__global__ void k_spmm(const int* __restrict__ rows, const int* __restrict__ cols,
                       const float* __restrict__ vals, int P) {
    long long t = (long long)blockIdx.x * blockDim.x + threadIdx.x;
    if (t >= (long long)P * 10) return;
    int e = (int)(t / 10);
    int q = (int)(t - (long long)e * 10);
    int r = __ldg(&rows[e]), c = __ldg(&cols[e]);
    float val = __ldg(&vals[e]);
    float4 v = __ldg(reinterpret_cast<const float4*>(g_h3) + (size_t)c * 10 + q);
    v.x *= val; v.y *= val; v.z *= val; v.w *= val;
    red_add_v4(g_hp + ((size_t)r * 10 + q) * 4, v);
}

// ---------------- final: z = hp*(1+c3); log_softmax -------------------------
__global__ void k_final(float* __restrict__ out) {
    int gt = blockIdx.x * blockDim.x + threadIdx.x;
    int w = gt >> 5;
    int lane = gt & 31;
    if (w >= NN) return;

    const float NEG_INF = __int_as_float(0xff800000);
    int c0 = lane, c1 = lane + 32;
    size_t base = (size_t)w * FO;

    float z0 = g_hp[base + c0] * (1.0f + g_c3[base + c0]);
    float z1 = (c1 < FO) ? g_hp[base + c1] * (1.0f + g_c3[base + c1]) : NEG_INF;

    float m = fmaxf(z0, z1);
#pragma unroll
    for (int off = 16; off > 0; off >>= 1)
        m = fmaxf(m, __shfl_xor_sync(0xffffffffu, m, off));

    float s = expf(z0 - m) + ((c1 < FO) ? expf(z1 - m) : 0.0f);
#pragma unroll
    for (int off = 16; off > 0; off >>= 1)
        s += __shfl_xor_sync(0xffffffffu, s, off);

    float lse = logf(s) + m;
    out[base + c0] = z0 - lse;
    if (c1 < FO) out[base + c1] = z1 - lse;
}

// ---------------- host launcher ---------------------------------------------
static inline int cdiv(long long a, int b) { return (int)((a + b - 1) / b); }

extern "C" void kernel_launch(void* const* d_in, const int* in_sizes, int n_in,
                              void* d_out, int out_size) {
    const float* x     = (const float*)d_in[0];
    const float* omega = (const float*)d_in[1];
    const int*   ei    = (const int*)d_in[2];
    const int*   prow  = (const int*)d_in[3];
    const int*   pcol  = (const int*)d_in[4];
    const float* pval  = (const float*)d_in[5];
    const float* Wg1 = (const float*)d_in[6];  const float* bg1 = (const float*)d_in[7];
    const float* Wg2 = (const float*)d_in[8];  const float* bg2 = (const float*)d_in[9];
    const float* Wg3 = (const float*)d_in[10]; const float* bg3 = (const float*)d_in[11];
    const float* Wc1 = (const float*)d_in[12]; const float* bc1 = (const float*)d_in[13];
    const float* Wc2 = (const float*)d_in[14]; const float* bc2 = (const float*)d_in[15];
    const float* Wc3 = (const float*)d_in[16]; const float* bc3 = (const float*)d_in[17];

    int E = in_sizes[2] / 2;
    int P = in_sizes[3];
    const int* src = ei;
    const int* dst = ei + E;

    uint32_t dk[4][2];
    for (int j = 0; j < 4; j++) {
        uint32_t a = 0u, b = (uint32_t)j;
        threefry2x32(0u, 7u, a, b);
        dk[j][0] = a; dk[j][1] = b;
    }

    void *p_cnt, *p_h2, *p_hs3, *p_hp, *p_c1, *p_c2, *p_c3;
    void *p_xb, *p_ob, *p_w1, *p_w2, *p_wc1, *p_wc2, *p_hsb1, *p_hsb2;
    cudaGetSymbolAddress(&p_cnt, g_cnt);
    cudaGetSymbolAddress(&p_h2, g_h2);     cudaGetSymbolAddress(&p_hs3, g_hs3);
    cudaGetSymbolAddress(&p_hp, g_hp);
    cudaGetSymbolAddress(&p_c1, g_c1);     cudaGetSymbolAddress(&p_c2, g_c2);
    cudaGetSymbolAddress(&p_c3, g_c3);
    cudaGetSymbolAddress(&p_xb, g_xb);     cudaGetSymbolAddress(&p_ob, g_ob);
    cudaGetSymbolAddress(&p_w1, g_w1);     cudaGetSymbolAddress(&p_w2, g_w2);
    cudaGetSymbolAddress(&p_wc1, g_wc1);   cudaGetSymbolAddress(&p_wc2, g_wc2);
    cudaGetSymbolAddress(&p_hsb1, g_hsb1); cudaGetSymbolAddress(&p_hsb2, g_hsb2);

    __nv_bfloat16* xb = (__nv_bfloat16*)p_xb;   // x bf16; reused as L2 GCN A
    __nv_bfloat16* ob = (__nv_bfloat16*)p_ob;   // omega bf16; reused as L2 comp A

    cudaStream_t st = 0;
    cudaMemsetAsync(p_cnt, 0, NN * sizeof(int), st);
    cudaMemsetAsync(p_hp,  0, (size_t)NN * FO * sizeof(float), st);

    dim3 blk(256);

    // ---- convert x/omega + W splits + hist fused; then scan + scatter ----
    const long long SPLIT_TOTAL = 2LL * MPAD * (FIN / 4) + FIN * FH + FH * FH
                                + FIN * FC + FC * FC + E;
    k_split_all<<<cdiv(SPLIT_TOTAL, 256), blk, 0, st>>>(x, omega, Wg1, Wg2, Wc1, Wc2,
                                                        dst, E);
    k_scan<<<1, 1024, 0, st>>>();
    k_scatter<<<cdiv(E, 256), blk, 0, st>>>(src, dst, E);

    int nodeBlocks = cdiv(NN, 8);
    int sgBlocks   = cdiv(NN, 64);

    // ---- fat GEMM #1 (bf16, K=512): GCN L1 + comp L1 (fp32 c1) ----
    GemmP g1{xb, (const __nv_bfloat16*)p_w1, nullptr, nullptr,
             (__nv_bfloat16*)p_hsb1, NN, FIN, FH, 1, 0};
    GemmP c1{ob, (const __nv_bfloat16*)p_wc1, bc1, (float*)p_c1,
             nullptr, NN, FIN, FC, 0, 1};
    k_gemm_fat<<<MT * 3, blk, 0, st>>>(g1, c1, 1, 3);

    // ---- fat: L1 CSR agg+finish -> xb || dropout(c1) -> ob (bf16) ----
    k_csr1<<<nodeBlocks + cdiv(MPAD * FC, 256), blk, 0, st>>>(
        (const __nv_bfloat16*)p_hsb1, bg1, xb,
        dk[0][0], dk[0][1], nodeBlocks,
        (const float*)p_c1, ob, dk[2][0], dk[2][1]);

    // ---- fat GEMM #2 (bf16): GCN L2 (K=128) + comp L2 (K=256, fp32 c2) ----
    GemmP g2{xb, (const __nv_bfloat16*)p_w2, nullptr, nullptr,
             (__nv_bfloat16*)p_hsb2, NN, FH, FH, 1, 0};
    GemmP c2{ob, (const __nv_bfloat16*)p_wc2, bc2, (float*)p_c2,
             nullptr, NN, FC, FC, 0, 1};
    k_gemm_fat<<<MT * 3, blk, 0, st>>>(g2, c2, 1, 3);

    // ---- fat: L2 CSR agg+finish -> h2 || comp L3 sgemm (dropout(c2)@Wc3) ----
    SgP sc3{(const float*)p_c2, Wc3, bc3, (float*)p_c3, FC, 0, 1, dk[3][0], dk[3][1]};
    k_csr2_sg<<<nodeBlocks + sgBlocks, blk, 0, st>>>(
        (const __nv_bfloat16*)p_hsb2, bg2, (float*)p_h2,
        dk[1][0], dk[1][1], nodeBlocks, sc3);

    // ---- GCN L3 sgemm: hs3 = dis * (h2 @ Wg3) ----
    SgP s3{(const float*)p_h2, Wg3, nullptr, (float*)p_hs3, FH, 1, 0, 0u, 0u};
    k_sgemm<<<sgBlocks, blk, 0, st>>>(s3);

    // ---- L3 CSR agg + finish -> h3 ----
    k_csr3<<<cdiv(NN * 10, 256), blk, 0, st>>>((const float*)p_hs3, bg3);

    // ---- SpMM with partition matrix ----
    k_spmm<<<cdiv((long long)P * 10, 256), blk, 0, st>>>(prow, pcol, pval, P);

    // ---- combine + log_softmax ----
    k_final<<<cdiv((long long)NN * 32, 256), blk, 0, st>>>((float*)d_out);
}

// round 17
// speedup vs baseline: 1.1442x; 1.1442x over previous
#include <cuda_runtime.h>
#include <cuda_bf16.h>
#include <stdint.h>

#define NN    50000
#define FIN   512
#define FH    128
#define FO    40
#define FC    256
#define MPAD  50048           // 391 * 128
#define MT    391
#define EMAX  800000

// ---------------- scratch (device globals; no allocation allowed) ----------
__device__ int   g_cnt[NN];
__device__ int   g_rowptr[NN + 1];
__device__ int   g_woff[NN];
__device__ int   g_eidx[EMAX];
__device__ float g_dis[NN];
__device__ float g_hs3[NN * FO];
__device__ float g_h3[NN * FO];
__device__ float g_hp[NN * FO];
__device__ float g_c1[NN * FC];
__device__ float g_c2[NN * FC];
__device__ float g_c3[NN * FO];
__device__ __nv_bfloat16 g_xb[(size_t)MPAD * FIN];   // x bf16; later: L2 GCN A
__device__ __nv_bfloat16 g_ob[(size_t)MPAD * FIN];   // omega bf16; later: L2 comp A
__device__ __nv_bfloat16 g_h2b[(size_t)MPAD * FH];   // bf16 h2 (L3 GCN A), pad rows stay 0
__device__ __nv_bfloat16 g_c2b[(size_t)MPAD * FC];   // bf16 dropout(c2) (L3 comp A)
__device__ __nv_bfloat16 g_w1[FH * FIN];
__device__ __nv_bfloat16 g_w2[FH * FH];
__device__ __nv_bfloat16 g_wc1[FC * FIN];
__device__ __nv_bfloat16 g_wc2[FC * FC];
__device__ __nv_bfloat16 g_wg3[128 * FH];            // rows 40..127 stay 0
__device__ __nv_bfloat16 g_wc3[128 * FC];            // rows 40..127 stay 0
__device__ __nv_bfloat16 g_hsb1[NN * FH];            // bf16 hs1 (sole copy)
__device__ __nv_bfloat16 g_hsb2[NN * FH];            // bf16 hs2 (sole copy)

// ---------------- threefry2x32 (JAX-compatible, partitionable) -------------
__host__ __device__ __forceinline__ void threefry2x32(uint32_t k0, uint32_t k1,
                                                      uint32_t& x0, uint32_t& x1) {
    uint32_t ks0 = k0, ks1 = k1, ks2 = k0 ^ k1 ^ 0x1BD11BDAu;
    x0 += ks0; x1 += ks1;
#define TF_RND(r) { x0 += x1; x1 = (x1 << (r)) | (x1 >> (32 - (r))); x1 ^= x0; }
    TF_RND(13) TF_RND(15) TF_RND(26) TF_RND(6)   x0 += ks1; x1 += ks2 + 1u;
    TF_RND(17) TF_RND(29) TF_RND(16) TF_RND(24)  x0 += ks2; x1 += ks0 + 2u;
    TF_RND(13) TF_RND(15) TF_RND(26) TF_RND(6)   x0 += ks0; x1 += ks1 + 3u;
    TF_RND(17) TF_RND(29) TF_RND(16) TF_RND(24)  x0 += ks1; x1 += ks2 + 4u;
    TF_RND(13) TF_RND(15) TF_RND(26) TF_RND(6)   x0 += ks2; x1 += ks0 + 5u;
#undef TF_RND
}

__device__ __forceinline__ bool tf_keep(uint32_t k0, uint32_t k1, uint32_t idx) {
    uint32_t x0 = 0u, x1 = idx;
    threefry2x32(k0, k1, x0, x1);
    return (((x0 ^ x1) >> 31) == 0u);
}

__device__ __forceinline__ void red_add_v4(float* p, float4 v) {
    asm volatile("red.global.add.v4.f32 [%0], {%1, %2, %3, %4};"
                 :: "l"(p), "f"(v.x), "f"(v.y), "f"(v.z), "f"(v.w) : "memory");
}

__device__ __forceinline__ uint32_t smem_u32(const void* p) {
    uint32_t a;
    asm("{ .reg .u64 t; cvta.to.shared.u64 t, %1; cvt.u32.u64 %0, t; }" : "=r"(a) : "l"(p));
    return a;
}

__device__ __forceinline__ void ldsm_x4(uint32_t* r, uint32_t addr) {
    asm volatile("ldmatrix.sync.aligned.m8n8.x4.shared.b16 {%0,%1,%2,%3}, [%4];"
                 : "=r"(r[0]), "=r"(r[1]), "=r"(r[2]), "=r"(r[3]) : "r"(addr));
}

__device__ __forceinline__ void mma16816(float* c, const uint32_t* a, const uint32_t* b) {
    asm volatile("mma.sync.aligned.m16n8k16.row.col.f32.bf16.bf16.f32 "
                 "{%0,%1,%2,%3}, {%4,%5,%6,%7}, {%8,%9}, {%0,%1,%2,%3};"
                 : "+f"(c[0]), "+f"(c[1]), "+f"(c[2]), "+f"(c[3])
                 : "r"(a[0]), "r"(a[1]), "r"(a[2]), "r"(a[3]), "r"(b[0]), "r"(b[1]));
}

__device__ __forceinline__ void cp_async16(uint32_t saddr, const void* gaddr) {
    asm volatile("cp.async.cg.shared.global [%0], [%1], 16;" :: "r"(saddr), "l"(gaddr));
}
#define CP_COMMIT() asm volatile("cp.async.commit_group;" ::: "memory")
#define CP_WAIT(n)  asm volatile("cp.async.wait_group %0;" :: "n"(n) : "memory")

// ---------------- CSR build --------------------------------------------------
__global__ void __launch_bounds__(1024) k_scan() {
    __shared__ int part[1024];
    int tid = threadIdx.x;
    const int CH = (NN + 1023) / 1024;
    int lo = tid * CH, hi = lo + CH > NN ? NN : lo + CH;
    int s = 0;
    for (int i = lo; i < hi; i++) s += g_cnt[i];
    part[tid] = s;
    __syncthreads();
    for (int off = 1; off < 1024; off <<= 1) {
        int t = (tid >= off) ? part[tid - off] : 0;
        __syncthreads();
        part[tid] += t;
        __syncthreads();
    }
    int run = part[tid] - s;
    for (int i = lo; i < hi; i++) {
        g_rowptr[i] = run;
        g_woff[i]   = run;
        g_dis[i]    = rsqrtf(1.0f + (float)g_cnt[i]);
        run += g_cnt[i];
    }
    if (tid == 1023) g_rowptr[NN] = run;
}

__global__ void k_scatter(const int* __restrict__ src, const int* __restrict__ dst, int E) {
    int i = blockIdx.x * blockDim.x + threadIdx.x;
    if (i >= E) return;
    int pos = atomicAdd(&g_woff[dst[i]], 1);
    g_eidx[pos] = src[i];
}

// ---------------- merged convert + W-split + hist pass ----------------------
__device__ __forceinline__ void convA_item4(const float* A, __nv_bfloat16* out,
                                            int K, long long i) {
    int K4 = K >> 2;
    int r = (int)(i / K4), kk = (int)(i - (long long)r * K4) * 4;
    __nv_bfloat162 h01, h23;
    if (r < NN) {
        float4 a = *reinterpret_cast<const float4*>(A + (size_t)r * K + kk);
        h01 = __halves2bfloat162(__float2bfloat16(a.x), __float2bfloat16(a.y));
        h23 = __halves2bfloat162(__float2bfloat16(a.z), __float2bfloat16(a.w));
    } else {
        __nv_bfloat16 z = __float2bfloat16(0.f);
        h01 = __halves2bfloat162(z, z); h23 = h01;
    }
    uint2 hv;
    hv.x = *reinterpret_cast<uint32_t*>(&h01);
    hv.y = *reinterpret_cast<uint32_t*>(&h23);
    *reinterpret_cast<uint2*>(out + (size_t)r * K + kk) = hv;
}

__device__ __forceinline__ void splitW_item(const float* W, __nv_bfloat16* out,
                                            int K, int N, int i) {
    int k = i / N, n = i - k * N;
    out[(size_t)n * K + k] = __float2bfloat16(W[(size_t)k * N + n]);
}

__global__ void k_split_all(const float* __restrict__ x, const float* __restrict__ omega,
                            const float* __restrict__ Wg1, const float* __restrict__ Wg2,
                            const float* __restrict__ Wc1, const float* __restrict__ Wc2,
                            const float* __restrict__ Wg3, const float* __restrict__ Wc3,
                            const int* __restrict__ dst, int E) {
    const long long R0 = (long long)MPAD * (FIN / 4);
    const long long R1 = R0;
    const long long R2 = FIN * FH, R3 = FH * FH;
    const long long R4 = FIN * FC, R5 = FC * FC;
    const long long R6 = FH * FO,  R7 = FC * FO;
    long long i = (long long)blockIdx.x * blockDim.x + threadIdx.x;
    if (i < R0) { convA_item4(x, g_xb, FIN, i); return; }
    i -= R0;
    if (i < R1) { convA_item4(omega, g_ob, FIN, i); return; }
    i -= R1;
    if (i < R2) { splitW_item(Wg1, g_w1, FIN, FH, (int)i); return; }
    i -= R2;
    if (i < R3) { splitW_item(Wg2, g_w2, FH, FH, (int)i); return; }
    i -= R3;
    if (i < R4) { splitW_item(Wc1, g_wc1, FIN, FC, (int)i); return; }
    i -= R4;
    if (i < R5) { splitW_item(Wc2, g_wc2, FC, FC, (int)i); return; }
    i -= R5;
    if (i < R6) { splitW_item(Wg3, g_wg3, FH, FO, (int)i); return; }
    i -= R6;
    if (i < R7) { splitW_item(Wc3, g_wc3, FC, FO, (int)i); return; }
    i -= R7;
    if (i < E) { atomicAdd(&g_cnt[dst[(int)i]], 1); return; }
}

// ---------------- bf16 GEMM (cp.async double-buffered) ----------------------
struct GemmP {
    const __nv_bfloat16* A; const __nv_bfloat16* B; const float* bias; float* C;
    __nv_bfloat16* Cb;
    int M, K, ldc, nvalid, scale, relu;
};

__device__ __forceinline__ void gemm_body(const GemmP& p, int bm, int bn) {
    __shared__ __align__(16) __nv_bfloat16 As[2][128][72];
    __shared__ __align__(16) __nv_bfloat16 Bs[2][128][72];

    int tid = threadIdx.x, wid = tid >> 5, lane = tid & 31;
    int wm = (wid & 3) << 5;
    int wn = (wid >> 2) << 6;

    float acc[2][8][4];
#pragma unroll
    for (int i = 0; i < 2; i++)
#pragma unroll
        for (int j = 0; j < 8; j++)
#pragma unroll
            for (int q = 0; q < 4; q++) acc[i][j][q] = 0.0f;

    int mat = lane >> 3, r8 = lane & 7;
    int nT = p.K >> 6;

    auto load_tile = [&](int t, int buf) {
        int k0 = t << 6;
#pragma unroll
        for (int i = 0; i < 4; i++) {
            int idx = tid + i * 256;
            int r = idx >> 3, c = idx & 7;
            cp_async16(smem_u32(&As[buf][r][c * 8]),
                       p.A + (size_t)(bm + r) * p.K + k0 + c * 8);
            cp_async16(smem_u32(&Bs[buf][r][c * 8]),
                       p.B + (size_t)(bn + r) * p.K + k0 + c * 8);
        }
        CP_COMMIT();
    };

    load_tile(0, 0);

    for (int t = 0; t < nT; t++) {
        int cur = t & 1;
        if (t + 1 < nT) {
            load_tile(t + 1, cur ^ 1);
            CP_WAIT(1);
        } else {
            CP_WAIT(0);
        }
        __syncthreads();

#pragma unroll
        for (int kk = 0; kk < 64; kk += 16) {
            uint32_t a[2][4];
#pragma unroll
            for (int mf = 0; mf < 2; mf++) {
                uint32_t addr = smem_u32(
                    &As[cur][wm + mf * 16 + ((mat & 1) << 3) + r8][kk + ((mat >> 1) << 3)]);
                ldsm_x4(a[mf], addr);
            }
            uint32_t b[8][2];
#pragma unroll
            for (int nf2 = 0; nf2 < 4; nf2++) {
                uint32_t addr = smem_u32(
                    &Bs[cur][wn + nf2 * 16 + ((mat >> 1) << 3) + r8][kk + ((mat & 1) << 3)]);
                uint32_t tr[4];
                ldsm_x4(tr, addr);
                b[nf2 * 2][0] = tr[0]; b[nf2 * 2][1] = tr[1];
                b[nf2 * 2 + 1][0] = tr[2]; b[nf2 * 2 + 1][1] = tr[3];
            }
#pragma unroll
            for (int mf = 0; mf < 2; mf++)
#pragma unroll
                for (int nf = 0; nf < 8; nf++)
                    mma16816(acc[mf][nf], a[mf], b[nf]);
        }
        __syncthreads();
    }

    int g = lane >> 2, tg = lane & 3;
#pragma unroll
    for (int mf = 0; mf < 2; mf++) {
#pragma unroll
        for (int half = 0; half < 2; half++) {
            int r = bm + wm + mf * 16 + g + half * 8;
            if (r >= p.M) continue;
            float sc = p.scale ? g_dis[r] : 1.0f;
#pragma unroll
            for (int nf = 0; nf < 8; nf++) {
                int c = bn + wn + nf * 8 + tg * 2;
                if (c >= p.nvalid) continue;
                float v0 = acc[mf][nf][half * 2 + 0];
                float v1 = acc[mf][nf][half * 2 + 1];
                if (p.bias) { v0 += p.bias[c]; v1 += p.bias[c + 1]; }
                if (p.relu) { v0 = fmaxf(v0, 0.0f); v1 = fmaxf(v1, 0.0f); }
                if (p.scale) { v0 *= sc; v1 *= sc; }
                if (p.C)
                    *reinterpret_cast<float2*>(&p.C[(size_t)r * p.ldc + c]) = make_float2(v0, v1);
                if (p.Cb)
                    *reinterpret_cast<__nv_bfloat162*>(&p.Cb[(size_t)r * p.ldc + c]) =
                        __halves2bfloat162(__float2bfloat16(v0), __float2bfloat16(v1));
            }
        }
    }
}

__global__ void __launch_bounds__(256, 2)
k_gemm_fat(GemmP pa, GemmP pb, int yA, int yTot) {
    int b = blockIdx.x;
    int y = b % yTot, m = b / yTot;
    if (y < yA) gemm_body(pa, m * 128, y * 128);
    else        gemm_body(pb, m * 128, (y - yA) * 128);
}

// ---------------- CSR warp-gather for F=128 ----------------------------------
__device__ __forceinline__ float4 bf16x4_to_f4(uint2 u) {
    __nv_bfloat162 p0 = *reinterpret_cast<__nv_bfloat162*>(&u.x);
    __nv_bfloat162 p1 = *reinterpret_cast<__nv_bfloat162*>(&u.y);
    return make_float4(__bfloat162float(p0.x), __bfloat162float(p0.y),
                       __bfloat162float(p1.x), __bfloat162float(p1.y));
}

__device__ __forceinline__ float4 csr_gather128(const __nv_bfloat16* hsb, int node, int lane) {
    int beg = g_rowptr[node], end = g_rowptr[node + 1];
    float4 acc = make_float4(0.f, 0.f, 0.f, 0.f);
    for (int e = beg; e < end; e++) {
        int s = g_eidx[e];
        float4 v = bf16x4_to_f4(
            __ldg(reinterpret_cast<const uint2*>(hsb + (size_t)s * 128 + lane * 4)));
        acc.x += v.x; acc.y += v.y; acc.z += v.z; acc.w += v.w;
    }
    return acc;
}

// fat: L1 CSR agg+finish -> bf16 xb (L2 GCN A)  ||  comp dropout c1 -> bf16 ob
__global__ void k_csr1(const __nv_bfloat16* __restrict__ hsb,
                       const float* __restrict__ b, __nv_bfloat16* __restrict__ out,
                       uint32_t k0, uint32_t k1, int nodeBlocks,
                       const float* __restrict__ cin, __nv_bfloat16* __restrict__ aout,
                       uint32_t ck0, uint32_t ck1) {
    if ((int)blockIdx.x < nodeBlocks) {
        int node = blockIdx.x * 8 + (threadIdx.x >> 5);
        if (node >= NN) return;
        int lane = threadIdx.x & 31;
        float4 acc = csr_gather128(hsb, node, lane);
        float di = g_dis[node];
        int base = node * 128 + lane * 4;
        float4 h = bf16x4_to_f4(*reinterpret_cast<const uint2*>(hsb + base));
        float4 bb = *reinterpret_cast<const float4*>(b + lane * 4);
        float v[4] = { di * (acc.x + h.x) + bb.x, di * (acc.y + h.y) + bb.y,
                       di * (acc.z + h.z) + bb.z, di * (acc.w + h.w) + bb.w };
        __nv_bfloat16 hi[4];
#pragma unroll
        for (int j = 0; j < 4; j++) {
            float t = fmaxf(v[j], 0.0f);
            t = tf_keep(k0, k1, (uint32_t)(base + j)) ? 2.0f * t : 0.0f;
            hi[j] = __float2bfloat16(t);
        }
        *reinterpret_cast<__nv_bfloat162*>(out + base)     = __halves2bfloat162(hi[0], hi[1]);
        *reinterpret_cast<__nv_bfloat162*>(out + base + 2) = __halves2bfloat162(hi[2], hi[3]);
    } else {
        int e = (blockIdx.x - nodeBlocks) * blockDim.x + threadIdx.x;
        if (e >= MPAD * FC) return;
        int r = e >> 8;
        __nv_bfloat16 h = __float2bfloat16(0.f);
        if (r < NN) {
            float v = tf_keep(ck0, ck1, (uint32_t)e) ? 2.0f * cin[e] : 0.0f;
            h = __float2bfloat16(v);
        }
        aout[e] = h;
    }
}

// fat: L2 CSR agg+finish -> bf16 h2b  ||  comp dropout c2 -> bf16 c2b
__global__ void k_csr2(const __nv_bfloat16* __restrict__ hsb,
                       const float* __restrict__ b, __nv_bfloat16* __restrict__ out,
                       uint32_t k0, uint32_t k1, int nodeBlocks,
                       const float* __restrict__ cin, __nv_bfloat16* __restrict__ aout,
                       uint32_t ck0, uint32_t ck1) {
    if ((int)blockIdx.x < nodeBlocks) {
        int node = blockIdx.x * 8 + (threadIdx.x >> 5);
        if (node >= NN) return;
        int lane = threadIdx.x & 31;
        float4 acc = csr_gather128(hsb, node, lane);
        float di = g_dis[node];
        int base = node * 128 + lane * 4;
        float4 h = bf16x4_to_f4(*reinterpret_cast<const uint2*>(hsb + base));
        float4 bb = *reinterpret_cast<const float4*>(b + lane * 4);
        float v[4] = { di * (acc.x + h.x) + bb.x, di * (acc.y + h.y) + bb.y,
                       di * (acc.z + h.z) + bb.z, di * (acc.w + h.w) + bb.w };
        __nv_bfloat16 hi[4];
#pragma unroll
        for (int j = 0; j < 4; j++) {
            float t = fmaxf(v[j], 0.0f);
            t = tf_keep(k0, k1, (uint32_t)(base + j)) ? 2.0f * t : 0.0f;
            hi[j] = __float2bfloat16(t);
        }
        *reinterpret_cast<__nv_bfloat162*>(out + base)     = __halves2bfloat162(hi[0], hi[1]);
        *reinterpret_cast<__nv_bfloat162*>(out + base + 2) = __halves2bfloat162(hi[2], hi[3]);
    } else {
        int e = (blockIdx.x - nodeBlocks) * blockDim.x + threadIdx.x;
        if (e >= NN * FC) return;   // pad rows of c2b stay statically zero
        float v = tf_keep(ck0, ck1, (uint32_t)e) ? 2.0f * cin[e] : 0.0f;
        aout[e] = __float2bfloat16(v);
    }
}

// L3: thread per (node, q<10): CSR gather float4 + finish -> h3
__global__ void k_csr3(const float* __restrict__ hs, const float* __restrict__ b) {
    int t = blockIdx.x * blockDim.x + threadIdx.x;
    if (t >= NN * 10) return;
    int node = t / 10, q = t - node * 10;
    int beg = g_rowptr[node], end = g_rowptr[node + 1];
    float4 acc = make_float4(0.f, 0.f, 0.f, 0.f);
    for (int e = beg; e < end; e++) {
        int s = g_eidx[e];
        float4 v = __ldg(reinterpret_cast<const float4*>(hs) + (size_t)s * 10 + q);
        acc.x += v.x; acc.y += v.y; acc.z += v.z; acc.w += v.w;
    }
    float di = g_dis[node];
    float4 h = __ldg(reinterpret_cast<const float4*>(hs) + (size_t)node * 10 + q);
    float4 bb = *reinterpret_cast<const float4*>(b + q * 4);
    float4 o;
    o.x = di * (acc.x + h.x) + bb.x;
    o.y = di * (acc.y + h.y) + bb.y;
    o.z = di * (acc.z + h.z) + bb.z;
    o.w = di * (acc.w + h.w) + bb.w;
    *reinterpret_cast<float4*>(g_h3 + (size_t)node * 40 + q * 4) = o;
}

// ---------------- SpMM -------------------------------------------------------
__global__ void k_spmm(const int* __restrict__ rows, const int* __restrict__ cols,
                       const float* __restrict__ vals, int P) {
    long long t = (long long)blockIdx.x * blockDim.x + threadIdx.x;
    if (t >= (long long)P * 10) return;
    int e = (int)(t / 10);
    int q = (int)(t - (long long)e * 10);
    int r = __ldg(&rows[e]), c = __ldg(&cols[e]);
    float val = __ldg(&vals[e]);
    float4 v = __ldg(reinterpret_cast<const float4*>(g_h3) + (size_t)c * 10 + q);
    v.x *= val; v.y *= val; v.z *= val; v.w *= val;
    red_add_v4(g_hp + ((size_t)r * 10 + q) * 4, v);
}

// ---------------- final: z = hp*(1+c3); log_softmax -------------------------
__global__ void k_final(float* __restrict__ out) {
    int gt = blockIdx.x * blockDim.x + threadIdx.x;
    int w = gt >> 5;
    int lane = gt & 31;
    if (w >= NN) return;

    const float NEG_INF = __int_as_float(0xff800000);
    int c0 = lane, c1 = lane + 32;
    size_t base = (size_t)w * FO;

    float z0 = g_hp[base + c0] * (1.0f + g_c3[base + c0]);
    float z1 = (c1 < FO) ? g_hp[base + c1] * (1.0f + g_c3[base + c1]) : NEG_INF;

    float m = fmaxf(z0, z1);
#pragma unroll
    for (int off = 16; off > 0; off >>= 1)
        m = fmaxf(m, __shfl_xor_sync(0xffffffffu, m, off));

    float s = expf(z0 - m) + ((c1 < FO) ? expf(z1 - m) : 0.0f);
#pragma unroll
    for (int off = 16; off > 0; off >>= 1)
        s += __shfl_xor_sync(0xffffffffu, s, off);

    float lse = logf(s) + m;
    out[base + c0] = z0 - lse;
    if (c1 < FO) out[base + c1] = z1 - lse;
}

// ---------------- host launcher ---------------------------------------------
static inline int cdiv(long long a, int b) { return (int)((a + b - 1) / b); }

extern "C" void kernel_launch(void* const* d_in, const int* in_sizes, int n_in,
                              void* d_out, int out_size) {
    const float* x     = (const float*)d_in[0];
    const float* omega = (const float*)d_in[1];
    const int*   ei    = (const int*)d_in[2];
    const int*   prow  = (const int*)d_in[3];
    const int*   pcol  = (const int*)d_in[4];
    const float* pval  = (const float*)d_in[5];
    const float* Wg1 = (const float*)d_in[6];  const float* bg1 = (const float*)d_in[7];
    const float* Wg2 = (const float*)d_in[8];  const float* bg2 = (const float*)d_in[9];
    const float* Wg3 = (const float*)d_in[10]; const float* bg3 = (const float*)d_in[11];
    const float* Wc1 = (const float*)d_in[12]; const float* bc1 = (const float*)d_in[13];
    const float* Wc2 = (const float*)d_in[14]; const float* bc2 = (const float*)d_in[15];
    const float* Wc3 = (const float*)d_in[16]; const float* bc3 = (const float*)d_in[17];

    int E = in_sizes[2] / 2;
    int P = in_sizes[3];
    const int* src = ei;
    const int* dst = ei + E;

    uint32_t dk[4][2];
    for (int j = 0; j < 4; j++) {
        uint32_t a = 0u, b = (uint32_t)j;
        threefry2x32(0u, 7u, a, b);
        dk[j][0] = a; dk[j][1] = b;
    }

    void *p_cnt, *p_hs3, *p_hp, *p_c1, *p_c2, *p_c3;
    void *p_xb, *p_ob, *p_h2b, *p_c2b;
    void *p_w1, *p_w2, *p_wc1, *p_wc2, *p_wg3, *p_wc3, *p_hsb1, *p_hsb2;
    cudaGetSymbolAddress(&p_cnt, g_cnt);
    cudaGetSymbolAddress(&p_hs3, g_hs3);
    cudaGetSymbolAddress(&p_hp, g_hp);
    cudaGetSymbolAddress(&p_c1, g_c1);     cudaGetSymbolAddress(&p_c2, g_c2);
    cudaGetSymbolAddress(&p_c3, g_c3);
    cudaGetSymbolAddress(&p_xb, g_xb);     cudaGetSymbolAddress(&p_ob, g_ob);
    cudaGetSymbolAddress(&p_h2b, g_h2b);   cudaGetSymbolAddress(&p_c2b, g_c2b);
    cudaGetSymbolAddress(&p_w1, g_w1);     cudaGetSymbolAddress(&p_w2, g_w2);
    cudaGetSymbolAddress(&p_wc1, g_wc1);   cudaGetSymbolAddress(&p_wc2, g_wc2);
    cudaGetSymbolAddress(&p_wg3, g_wg3);   cudaGetSymbolAddress(&p_wc3, g_wc3);
    cudaGetSymbolAddress(&p_hsb1, g_hsb1); cudaGetSymbolAddress(&p_hsb2, g_hsb2);

    __nv_bfloat16* xb  = (__nv_bfloat16*)p_xb;
    __nv_bfloat16* ob  = (__nv_bfloat16*)p_ob;
    __nv_bfloat16* h2b = (__nv_bfloat16*)p_h2b;
    __nv_bfloat16* c2b = (__nv_bfloat16*)p_c2b;

    cudaStream_t st = 0;
    cudaMemsetAsync(p_cnt, 0, NN * sizeof(int), st);
    cudaMemsetAsync(p_hp,  0, (size_t)NN * FO * sizeof(float), st);

    dim3 blk(256);

    // ---- convert x/omega + W splits (incl. L3 Ws) + hist; scan; scatter ----
    const long long SPLIT_TOTAL = 2LL * MPAD * (FIN / 4) + FIN * FH + FH * FH
                                + FIN * FC + FC * FC + FH * FO + FC * FO + E;
    k_split_all<<<cdiv(SPLIT_TOTAL, 256), blk, 0, st>>>(x, omega, Wg1, Wg2, Wc1, Wc2,
                                                        Wg3, Wc3, dst, E);
    k_scan<<<1, 1024, 0, st>>>();
    k_scatter<<<cdiv(E, 256), blk, 0, st>>>(src, dst, E);

    int nodeBlocks = cdiv(NN, 8);

    // ---- fat GEMM #1 (bf16, K=512): GCN L1 + comp L1 (fp32 c1) ----
    GemmP g1{xb, (const __nv_bfloat16*)p_w1, nullptr, nullptr,
             (__nv_bfloat16*)p_hsb1, NN, FIN, FH, FH, 1, 0};
    GemmP c1{ob, (const __nv_bfloat16*)p_wc1, bc1, (float*)p_c1,
             nullptr, NN, FIN, FC, FC, 0, 1};
    k_gemm_fat<<<MT * 3, blk, 0, st>>>(g1, c1, 1, 3);

    // ---- fat: L1 CSR agg+finish -> xb || dropout(c1) -> ob (bf16) ----
    k_csr1<<<nodeBlocks + cdiv(MPAD * FC, 256), blk, 0, st>>>(
        (const __nv_bfloat16*)p_hsb1, bg1, xb,
        dk[0][0], dk[0][1], nodeBlocks,
        (const float*)p_c1, ob, dk[2][0], dk[2][1]);

    // ---- fat GEMM #2 (bf16): GCN L2 (K=128) + comp L2 (K=256, fp32 c2) ----
    GemmP g2{xb, (const __nv_bfloat16*)p_w2, nullptr, nullptr,
             (__nv_bfloat16*)p_hsb2, NN, FH, FH, FH, 1, 0};
    GemmP c2{ob, (const __nv_bfloat16*)p_wc2, bc2, (float*)p_c2,
             nullptr, NN, FC, FC, FC, 0, 1};
    k_gemm_fat<<<MT * 3, blk, 0, st>>>(g2, c2, 1, 3);

    // ---- fat: L2 CSR agg+finish -> h2b (bf16) || dropout(c2) -> c2b (bf16) ----
    k_csr2<<<nodeBlocks + cdiv(NN * FC, 256), blk, 0, st>>>(
        (const __nv_bfloat16*)p_hsb2, bg2, h2b,
        dk[1][0], dk[1][1], nodeBlocks,
        (const float*)p_c2, c2b, dk[3][0], dk[3][1]);

    // ---- fat GEMM #3 (bf16, N=40 in 128-tile): GCN L3 (scale) + comp L3 (bias)
    GemmP g3{h2b, (const __nv_bfloat16*)p_wg3, nullptr, (float*)p_hs3,
             nullptr, NN, FH, FO, FO, 1, 0};
    GemmP c3{c2b, (const __nv_bfloat16*)p_wc3, bc3, (float*)p_c3,
             nullptr, NN, FC, FO, FO, 0, 0};
    k_gemm_fat<<<MT * 2, blk, 0, st>>>(g3, c3, 1, 2);

    // ---- L3 CSR agg + finish -> h3 ----
    k_csr3<<<cdiv(NN * 10, 256), blk, 0, st>>>((const float*)p_hs3, bg3);

    // ---- SpMM with partition matrix ----
    k_spmm<<<cdiv((long long)P * 10, 256), blk, 0, st>>>(prow, pcol, pval, P);

    // ---- combine + log_softmax ----
    k_final<<<cdiv((long long)NN * 32, 256), blk, 0, st>>>((float*)d_out);
}